// round 11
// baseline (speedup 1.0000x reference)
#include <cuda_runtime.h>

#define AALPHA 0.42f
#define IMG_H 1024
#define IMG_W 1024
#define NIMG 48     // 16 batches * 3 masks
#define RPB 64      // output rows per block
#define BPI 16      // blocks per image (IMG_H / RPB)

__device__ float g_part[NIMG * BPI];
__device__ float g_weights[NIMG];

// ---- FFMA-imm helpers: immediate multiplier form has rt_SMSP=1 (vs FADD=2).
// a+b and a-b via fma(x, +-1.0, y) are EXACT.
__device__ __forceinline__ float f_add(float a, float b) {
    float r; asm("fma.rn.f32 %0, %1, 0F3F800000, %2;" : "=f"(r) : "f"(a), "f"(b)); return r;
}
__device__ __forceinline__ float f_sub(float a, float b) {   // a - b
    float r; asm("fma.rn.f32 %0, %1, 0FBF800000, %2;" : "=f"(r) : "f"(b), "f"(a)); return r;
}
__device__ __forceinline__ float f_fma2(float x, float c) {  // 2*x + c
    float r; asm("fma.rn.f32 %0, %1, 0F40000000, %2;" : "=f"(r) : "f"(x), "f"(c)); return r;
}
__device__ __forceinline__ float f_fman6(float x, float c) { // -6*x + c
    float r; asm("fma.rn.f32 %0, %1, 0FC0C00000, %2;" : "=f"(r) : "f"(x), "f"(c)); return r;
}
__device__ __forceinline__ float f_fmad49(float v, float c) { // c - v/49
    float r; asm("fma.rn.f32 %0, %1, 0FBCA72F05, %2;" : "=f"(r) : "f"(v), "f"(c)); return r;
}

// sigmoid(x) = 0.5*tanh(x/2)+0.5, all scales in imm-fma form
__device__ __forceinline__ float fsig(float x) {
    float r;
    asm("{\n\t"
        ".reg .f32 t;\n\t"
        "fma.rn.f32 t, %1, 0F3F000000, 0F00000000;\n\t"
        "tanh.approx.f32 t, t;\n\t"
        "fma.rn.f32 %0, t, 0F3F000000, 0F3F000000;\n\t"
        "}" : "=f"(r) : "f"(x));
    return r;
}
__device__ __forceinline__ float fsqrt_fast(float x) {
    float r; asm("sqrt.approx.f32 %0, %1;" : "=f"(r) : "f"(x)); return r;
}

// ---------------------------------------------------------------------------
// score = ALPHA * sum(edge) + (1-ALPHA)/49 * sum( cnt(p) * (m_p - mean_p)^2 )
// R10 pipelined structure; clean-path arithmetic converted to FFMA-imm (rt=1)
// to relieve the fma pipe (the measured binder).
// ---------------------------------------------------------------------------
__global__ __launch_bounds__(256, 2) void score_kernel(const float* __restrict__ logits) {
    __shared__ float rowbuf[4][1032];   // cols -4..1027, data at offset 4
    __shared__ float red[8];

    const int img = blockIdx.y;
    const int y0  = blockIdx.x * RPB;
    const int t   = threadIdx.x;
    const int c0  = t * 4;
    const float* base = logits + (size_t)img * (IMG_H * IMG_W);

    // zero pad columns of all four buffers (written once)
    if (t < 32) {
        int b = t >> 3, j = t & 7;
        rowbuf[b][(j < 4) ? j : (1020 + j)] = 0.0f;
    }

    float hr[8][4];                      // horizontal-7-sum ring
    float rs[4][4], rt[4][4], rc[4][4];  // conv combo ring
    float vs[4] = {0.f, 0.f, 0.f, 0.f};
    #pragma unroll
    for (int k = 0; k < 8; ++k) { hr[k][0]=hr[k][1]=hr[k][2]=hr[k][3]=0.f; }
    #pragma unroll
    for (int k = 0; k < 4; ++k) {
        #pragma unroll
        for (int j = 0; j < 4; ++j) { rs[k][j]=0.f; rt[k][j]=0.f; rc[k][j]=0.f; }
    }

    float acc;

// consume one row from registers A,B,C (LDS'd pre-barrier). U static.
#define CONS_ROW(U, A, B, C, DOOUT, ACCV, ACCE, ACCL)                       \
    do {                                                                    \
        float h0 = f_add(f_add(f_add(A.y, A.z), f_add(A.w, B.x)),           \
                         f_add(f_add(B.y, B.z), B.w));                      \
        float h1 = f_add(h0, f_sub(C.x, A.y));                              \
        float h2 = f_add(h1, f_sub(C.y, A.z));                              \
        float h3 = f_add(h2, f_sub(C.z, A.w));                              \
        vs[0] = f_add(vs[0], f_sub(h0, hr[((U) + 1) & 7][0]));              \
        vs[1] = f_add(vs[1], f_sub(h1, hr[((U) + 1) & 7][1]));              \
        vs[2] = f_add(vs[2], f_sub(h2, hr[((U) + 1) & 7][2]));              \
        vs[3] = f_add(vs[3], f_sub(h3, hr[((U) + 1) & 7][3]));              \
        hr[(U) & 7][0] = h0; hr[(U) & 7][1] = h1;                           \
        hr[(U) & 7][2] = h2; hr[(U) & 7][3] = h3;                           \
        if (DOOUT) {                                                        \
            const int T = (U) & 3, M = ((U) + 1) & 3, Bo = ((U) + 2) & 3;   \
            _Pragma("unroll")                                               \
            for (int j = 0; j < 4; ++j) {                                   \
                float gxv = f_fma2(rt[M][j], f_add(rt[T][j], rt[Bo][j]));   \
                float gyv = f_sub(rs[T][j], rs[Bo][j]);                     \
                float lap = f_fman6(rc[M][j],                               \
                                    f_add(f_add(rc[T][j], rc[Bo][j]),       \
                                          rs[M][j]));                       \
                ACCE = f_add(ACCE,                                          \
                             fsqrt_fast(fmaf(gxv, gxv, gyv * gyv)));        \
                ACCL += fabsf(lap);                                         \
                float d = f_fmad49(vs[j], rc[M][j]);                        \
                (ACCV)[j] = fmaf(d, d, (ACCV)[j]);                          \
            }                                                               \
        }                                                                   \
        const int W = (U) & 3;                                              \
        rs[W][0] = f_fma2(B.x, f_add(A.w, B.y)); rt[W][0] = f_sub(A.w, B.y); rc[W][0] = B.x; \
        rs[W][1] = f_fma2(B.y, f_add(B.x, B.z)); rt[W][1] = f_sub(B.x, B.z); rc[W][1] = B.y; \
        rs[W][2] = f_fma2(B.z, f_add(B.y, B.w)); rt[W][2] = f_sub(B.y, B.w); rc[W][2] = B.z; \
        rs[W][3] = f_fma2(B.w, f_add(B.z, C.x)); rt[W][3] = f_sub(B.z, C.x); rc[W][3] = B.w; \
    } while (0)

    if (blockIdx.x >= 1 && blockIdx.x <= 14) {
        // ================= clean path: all rows in-bounds, chf = 7 =========
        float accv[4] = {0.f, 0.f, 0.f, 0.f};
        float acc_e = 0.f, acc_l = 0.f;

        const float* rp = base + (size_t)(y0 - 3) * IMG_W + c0;
        float4 cur0 = *(const float4*)rp;
        float4 cur1 = *(const float4*)(rp + IMG_W);
        rp += 2 * IMG_W;

// pair-iteration: consume rows UC,UC+1 from buf-pair BC (LDS before BAR),
// store current pair into buf-pair BS, prefetch next pair. All flags static.
#define PAIRX(UC, BS, BC, DOCONS, DOOUT, DOSTORE, DOPREF)                   \
    do {                                                                    \
        float4 n0, n1;                                                      \
        if (DOPREF) {                                                       \
            n0 = *(const float4*)rp;                                        \
            n1 = *(const float4*)(rp + IMG_W);                              \
            rp += 2 * IMG_W;                                                \
        }                                                                   \
        float4 A0, B0, C0, A1, B1, C1;                                      \
        if (DOCONS) {                                                       \
            const float* rb0 = rowbuf[2 * (BC)];                            \
            const float* rb1 = rowbuf[2 * (BC) + 1];                        \
            A0 = *(const float4*)(rb0 + c0);                                \
            B0 = *(const float4*)(rb0 + c0 + 4);                            \
            C0 = *(const float4*)(rb0 + c0 + 8);                            \
            A1 = *(const float4*)(rb1 + c0);                                \
            B1 = *(const float4*)(rb1 + c0 + 4);                            \
            C1 = *(const float4*)(rb1 + c0 + 8);                            \
        }                                                                   \
        if (DOSTORE) {                                                      \
            float a0 = fsig(cur0.x), a1 = fsig(cur0.y);                     \
            float a2 = fsig(cur0.z), a3 = fsig(cur0.w);                     \
            float b0 = fsig(cur1.x), b1 = fsig(cur1.y);                     \
            float b2 = fsig(cur1.z), b3 = fsig(cur1.w);                     \
            *(float4*)(rowbuf[2 * (BS)] + 4 + c0) =                         \
                make_float4(a0, a1, a2, a3);                                \
            *(float4*)(rowbuf[2 * (BS) + 1] + 4 + c0) =                     \
                make_float4(b0, b1, b2, b3);                                \
        }                                                                   \
        __syncthreads();                                                    \
        if (DOCONS) {                                                       \
            CONS_ROW((UC),     A0, B0, C0, DOOUT, accv, acc_e, acc_l);      \
            CONS_ROW((UC) + 1, A1, B1, C1, DOOUT, accv, acc_e, acc_l);      \
        }                                                                   \
        if (DOPREF) { cur0 = n0; cur1 = n1; }                               \
    } while (0)

        // k=0: store rows 0,1; prefetch 2,3; no consume
        PAIRX(0, 0, 0, false, false, true, true);
        // k=1..4: consume rows 0..7 (outputs at 6,7)
        PAIRX(0, 1, 0, true, false, true, true);
        PAIRX(2, 0, 1, true, false, true, true);
        PAIRX(4, 1, 0, true, false, true, true);
        PAIRX(6, 0, 1, true, true,  true, true);
        // k=5..32: consume rows 8..63, all outputs
        for (int ii = 0; ii < 7; ++ii) {
            PAIRX(0, 1, 0, true, true, true, true);
            PAIRX(2, 0, 1, true, true, true, true);
            PAIRX(4, 1, 0, true, true, true, true);
            PAIRX(6, 0, 1, true, true, true, true);
        }
        // k=33: consume 64,65; store 66,67; prefetch 68,69
        PAIRX(0, 1, 0, true, true, true, true);
        // k=34: consume 66,67; store 68,69; no prefetch
        PAIRX(2, 0, 1, true, true, true, false);
        // k=35: drain — consume 68,69 only
        PAIRX(4, 1, 0, true, true, false, false);
#undef PAIRX

        // fold cw/7 per column and 0.5*|lap| at the end
        float acc_v_tot = 0.f;
        #pragma unroll
        for (int j = 0; j < 4; ++j) {
            int col = c0 + j;
            float cwn = (float)(min(col, 3) + min(IMG_W - 1 - col, 3) + 1) * (1.0f / 7.0f);
            acc_v_tot = fmaf(accv[j], cwn, acc_v_tot);
        }
        float acc_e_tot = fmaf(0.5f, acc_l, acc_e);
        acc = AALPHA * acc_e_tot + ((1.0f - AALPHA) / 49.0f) * 7.0f * acc_v_tot;
    } else {
        // ================= guarded path (blocks 0 and 15), per-row =========
        float acc_e = 0.f, acc_l = 0.f, acc_v = 0.f;
        float cwf[4];
        #pragma unroll
        for (int j = 0; j < 4; ++j) {
            int col = c0 + j;
            cwf[j] = (float)(min(col, 3) + min(IMG_W - 1 - col, 3) + 1);
        }

        float4 cur = make_float4(0.f, 0.f, 0.f, 0.f);
        {
            int gy = y0 - 3;
            if ((unsigned)gy < IMG_H)
                cur = *(const float4*)(base + (size_t)gy * IMG_W + c0);
        }
        for (int ii = 0; ii < 72; ii += 8) {
            #pragma unroll
            for (int u = 0; u < 8; ++u) {
                const int i  = ii + u;
                const int gy = y0 - 3 + i;
                const bool valid = ((unsigned)gy < IMG_H) && (i < 70);

                float4 nxt = make_float4(0.f, 0.f, 0.f, 0.f);
                {
                    int gyn = gy + 1;
                    if ((unsigned)gyn < IMG_H && (i + 1) < 70)
                        nxt = *(const float4*)(base + (size_t)gyn * IMG_W + c0);
                }
                float m0 = valid ? fsig(cur.x) : 0.f;
                float m1 = valid ? fsig(cur.y) : 0.f;
                float m2 = valid ? fsig(cur.z) : 0.f;
                float m3 = valid ? fsig(cur.w) : 0.f;
                float* rb = rowbuf[u & 1];
                *(float4*)(rb + 4 + c0) = make_float4(m0, m1, m2, m3);
                __syncthreads();

                const float4 A = *(const float4*)(rb + c0);
                const float4 C = *(const float4*)(rb + c0 + 8);

                float h0 = ((A.y + A.z) + (A.w + m0)) + ((m1 + m2) + m3);
                float h1 = h0 + C.x - A.y;
                float h2 = h1 + C.y - A.z;
                float h3 = h2 + C.z - A.w;

                vs[0] += h0 - hr[(u + 1) & 7][0];
                vs[1] += h1 - hr[(u + 1) & 7][1];
                vs[2] += h2 - hr[(u + 1) & 7][2];
                vs[3] += h3 - hr[(u + 1) & 7][3];
                hr[u][0] = h0; hr[u][1] = h1; hr[u][2] = h2; hr[u][3] = h3;

                if (i >= 6 && i < 70) {
                    const int yo = gy - 3;
                    const float chf = (float)(min(yo, 3) + min(IMG_H - 1 - yo, 3) + 1);
                    const int T = u & 3, M = (u + 1) & 3, Bo = (u + 2) & 3;
                    float rowv = 0.f;
                    #pragma unroll
                    for (int j = 0; j < 4; ++j) {
                        float gxv = fmaf(2.f, rt[M][j], rt[T][j] + rt[Bo][j]);
                        float gyv = rs[T][j] - rs[Bo][j];
                        float lap = fmaf(-6.f, rc[M][j], (rc[T][j] + rc[Bo][j]) + rs[M][j]);
                        acc_e += fsqrt_fast(fmaf(gxv, gxv, gyv * gyv));
                        acc_l += fabsf(lap);
                        float d = fmaf(-(1.f / 49.f), vs[j], rc[M][j]);
                        rowv = fmaf(d * cwf[j], d, rowv);
                    }
                    acc_v += chf * rowv;
                }

                const int W = u & 3;
                rs[W][0] = fmaf(2.f, m0, A.w + m1); rt[W][0] = A.w - m1; rc[W][0] = m0;
                rs[W][1] = fmaf(2.f, m1, m0 + m2);  rt[W][1] = m0 - m2;  rc[W][1] = m1;
                rs[W][2] = fmaf(2.f, m2, m1 + m3);  rt[W][2] = m1 - m3;  rc[W][2] = m2;
                rs[W][3] = fmaf(2.f, m3, m2 + C.x); rt[W][3] = m2 - C.x; rc[W][3] = m3;

                cur = nxt;
            }
        }
        float acc_e_tot = fmaf(0.5f, acc_l, acc_e);
        acc = AALPHA * acc_e_tot + ((1.0f - AALPHA) / 49.0f) * acc_v;
    }
#undef CONS_ROW

    // block reduction -> per-block partial
    #pragma unroll
    for (int off = 16; off; off >>= 1)
        acc += __shfl_down_sync(0xffffffffu, acc, off);
    if ((t & 31) == 0) red[t >> 5] = acc;
    __syncthreads();
    if (t < 8) {
        float v = red[t];
        #pragma unroll
        for (int off = 4; off; off >>= 1)
            v += __shfl_down_sync(0xffu, v, off);
        if (t == 0) g_part[img * BPI + blockIdx.x] = v;
    }
}

// ---------------------------------------------------------------------------
// reduce partials; weights[b,s] = 0.5*(score/(sum+1e-6) + softmax(lw)[s])
// ---------------------------------------------------------------------------
__global__ void weights_kernel(const float* __restrict__ lw) {
    __shared__ float ss[NIMG];
    __shared__ float soft[3];
    int tid = threadIdx.x;
    if (tid < NIMG) {
        float s = 0.f;
        #pragma unroll
        for (int k = 0; k < BPI; ++k) s += g_part[tid * BPI + k];
        ss[tid] = s;
    }
    if (tid == 0) {
        float a = lw[0], b = lw[1], c = lw[2];
        float m = fmaxf(a, fmaxf(b, c));
        float e0 = expf(a - m), e1 = expf(b - m), e2 = expf(c - m);
        float inv = 1.0f / (e0 + e1 + e2);
        soft[0] = e0 * inv; soft[1] = e1 * inv; soft[2] = e2 * inv;
    }
    __syncthreads();
    if (tid < NIMG) {
        int b = tid / 3;
        int s = tid - b * 3;
        float denom = ss[b * 3] + ss[b * 3 + 1] + ss[b * 3 + 2] + 1e-6f;
        g_weights[tid] = (ss[tid] / denom + soft[s]) * 0.5f;
    }
}

// ---------------------------------------------------------------------------
// fused[b,p] = sum_s logits[b,s,p] * w[b,s]   (float4 vectorized)
// ---------------------------------------------------------------------------
__global__ __launch_bounds__(256) void fuse_kernel(const float* __restrict__ logits,
                                                   float* __restrict__ out) {
    const int N = IMG_H * IMG_W;
    int b = blockIdx.y;
    int i = blockIdx.x * blockDim.x + threadIdx.x;   // over N/4
    float w0 = g_weights[b * 3 + 0];
    float w1 = g_weights[b * 3 + 1];
    float w2 = g_weights[b * 3 + 2];
    const float4* p0 = (const float4*)(logits + (size_t)(b * 3 + 0) * N);
    const float4* p1 = (const float4*)(logits + (size_t)(b * 3 + 1) * N);
    const float4* p2 = (const float4*)(logits + (size_t)(b * 3 + 2) * N);
    float4 a = p0[i], bb = p1[i], cc = p2[i];
    float4 o;
    o.x = a.x * w0 + bb.x * w1 + cc.x * w2;
    o.y = a.y * w0 + bb.y * w1 + cc.y * w2;
    o.z = a.z * w0 + bb.z * w1 + cc.z * w2;
    o.w = a.w * w0 + bb.w * w1 + cc.w * w2;
    ((float4*)out)[(size_t)b * (N / 4) + i] = o;
}

extern "C" void kernel_launch(void* const* d_in, const int* in_sizes, int n_in,
                              void* d_out, int out_size) {
    const float* logits = (const float*)d_in[0];   // (16,3,1024,1024) fp32
    const float* lw     = (const float*)d_in[1];   // (3,) fp32
    float* out          = (float*)d_out;           // (16,1024,1024) fp32

    score_kernel<<<dim3(BPI, NIMG), 256>>>(logits);
    weights_kernel<<<1, 64>>>(lw);
    fuse_kernel<<<dim3((IMG_H * IMG_W / 4) / 256, 16), 256>>>(logits, out);
}

// round 13
// speedup vs baseline: 1.0267x; 1.0267x over previous
#include <cuda_runtime.h>

#define AALPHA 0.42f
#define IMG_H 1024
#define IMG_W 1024
#define NIMG 48     // 16 batches * 3 masks
#define RPB 64      // output rows per block
#define BPI 16      // blocks per image (IMG_H / RPB)

#define QS 1048576.0f            // 2^20 quantization scale
#define SE (1.0f / 1048576.0f)   // edge descale
#define SV (1.0f / (49.0f * 1048576.0f))  // d descale (d_i = 49*m_i - vs_i)

__device__ float g_part[NIMG * BPI];
__device__ float g_weights[NIMG];

// quantized sigmoid: round(sigmoid(x) * 2^20)  (1 MUFU + 1 fma + 1 cvt)
__device__ __forceinline__ int fsig_q(float x) {
    float t;
    asm("tanh.approx.f32 %0, %1;" : "=f"(t) : "f"(0.5f * x));
    return __float2int_rn(fmaf(0.5f * QS, t, 0.5f * QS));
}
__device__ __forceinline__ float fsqrt_fast(float x) {
    float r; asm("sqrt.approx.f32 %0, %1;" : "=f"(r) : "f"(x)); return r;
}

// ---------------------------------------------------------------------------
// score = ALPHA * sum(edge) + (1-ALPHA)/49 * sum( cnt(p) * (m_p - mean_p)^2 )
// Fixed-point pipeline: sigmoid quantized to int (x 2^20); ALL window sums
// and 3x3 convs exact in int32 (IADD3/LEA/IMAD spread over alu+fma pipes);
// floats only at sqrt / d^2 / accumulators. R10 pair-pipelined structure.
// Ranges: h<=7*2^20, vs<=49*2^20, |gx|<=4*2^20, |lap|<=6*2^20 - all safe.
// Halo layout: buffer index = col + 4; left halo cols -4..-1 -> idx 0..3,
// right halo cols 1024..1027 -> idx 1028..1031. BOTH are zeroed here (the
// R12 bug: right halo idx 1028..1031 was never initialized -> nondet junk).
// ---------------------------------------------------------------------------
__global__ __launch_bounds__(256, 2) void score_kernel(const float* __restrict__ logits) {
    __shared__ int rowbuf[4][1032];   // quantized m, cols -4..1027, data at +4
    __shared__ float red[8];

    const int img = blockIdx.y;
    const int y0  = blockIdx.x * RPB;
    const int t   = threadIdx.x;
    const int c0  = t * 4;
    const float* base = logits + (size_t)img * (IMG_H * IMG_W);

    // zero halo columns of all four buffers (written once, never overwritten)
    if (t < 32) {
        int b = t >> 3, j = t & 7;
        rowbuf[b][(j < 4) ? j : (1024 + j)] = 0;   // {0..3, 1028..1031}
    }

    int hr[8][4];                        // horizontal-7-sum ring (int)
    int rsi[4][4], rti[4][4], rci[4][4]; // conv combo ring (int, exact)
    int vs[4] = {0, 0, 0, 0};
    #pragma unroll
    for (int k = 0; k < 8; ++k) { hr[k][0]=hr[k][1]=hr[k][2]=hr[k][3]=0; }
    #pragma unroll
    for (int k = 0; k < 4; ++k) {
        #pragma unroll
        for (int j = 0; j < 4; ++j) { rsi[k][j]=0; rti[k][j]=0; rci[k][j]=0; }
    }

    float cwf[4];   // raw column coverage counts (<=7)
    #pragma unroll
    for (int j = 0; j < 4; ++j) {
        int col = c0 + j;
        cwf[j] = (float)(min(col, 3) + min(IMG_W - 1 - col, 3) + 1);
    }

    float acc;

// consume one row from int registers A,B,C (LDS'd pre-barrier). U static.
// ACCV = per-col f32 d_i^2 accumulators; ACCE/ACCL f32 (scaled by 2^20).
#define CONS_ROW(U, A, B, C, DOOUT, ACCV, ACCE, ACCL)                       \
    do {                                                                    \
        int h0 = ((A.y + A.z) + (A.w + B.x)) + ((B.y + B.z) + B.w);         \
        int h1 = h0 + C.x - A.y;                                            \
        int h2 = h1 + C.y - A.z;                                            \
        int h3 = h2 + C.z - A.w;                                            \
        vs[0] += h0 - hr[((U) + 1) & 7][0];                                 \
        vs[1] += h1 - hr[((U) + 1) & 7][1];                                 \
        vs[2] += h2 - hr[((U) + 1) & 7][2];                                 \
        vs[3] += h3 - hr[((U) + 1) & 7][3];                                 \
        hr[(U) & 7][0] = h0; hr[(U) & 7][1] = h1;                           \
        hr[(U) & 7][2] = h2; hr[(U) & 7][3] = h3;                           \
        if (DOOUT) {                                                        \
            const int T = (U) & 3, M = ((U) + 1) & 3, Bo = ((U) + 2) & 3;   \
            int lrow = 0;                                                   \
            _Pragma("unroll")                                               \
            for (int j = 0; j < 4; ++j) {                                   \
                int gxi = rti[T][j] + 2 * rti[M][j] + rti[Bo][j];           \
                int gyi = rsi[T][j] - rsi[Bo][j];                           \
                int lpi = (rci[T][j] + rci[Bo][j]) + rsi[M][j]              \
                          - 6 * rci[M][j];                                  \
                float gxf = __int2float_rn(gxi);                            \
                float gyf = __int2float_rn(gyi);                            \
                ACCE += fsqrt_fast(fmaf(gxf, gxf, gyf * gyf));              \
                lrow += abs(lpi);                                           \
                int di = 49 * rci[M][j] - vs[j];                            \
                float df = __int2float_rn(di);                              \
                (ACCV)[j] = fmaf(df, df, (ACCV)[j]);                        \
            }                                                               \
            ACCL += __int2float_rn(lrow);                                   \
        }                                                                   \
        const int W = (U) & 3;                                              \
        rsi[W][0] = 2 * B.x + (A.w + B.y); rti[W][0] = A.w - B.y; rci[W][0] = B.x; \
        rsi[W][1] = 2 * B.y + (B.x + B.z); rti[W][1] = B.x - B.z; rci[W][1] = B.y; \
        rsi[W][2] = 2 * B.z + (B.y + B.w); rti[W][2] = B.y - B.w; rci[W][2] = B.z; \
        rsi[W][3] = 2 * B.w + (B.z + C.x); rti[W][3] = B.z - C.x; rci[W][3] = B.w; \
    } while (0)

    if (blockIdx.x >= 1 && blockIdx.x <= 14) {
        // ================= clean path: all rows in-bounds, ch = 7 ==========
        float accv[4] = {0.f, 0.f, 0.f, 0.f};
        float acc_e = 0.f, acc_l = 0.f;

        const float* rp = base + (size_t)(y0 - 3) * IMG_W + c0;
        float4 cur0 = *(const float4*)rp;
        float4 cur1 = *(const float4*)(rp + IMG_W);
        rp += 2 * IMG_W;

// pair-iteration (R10): consume rows UC,UC+1 from buf-pair BC (LDS pre-BAR),
// store current pair into buf-pair BS, prefetch next pair. Flags static.
#define PAIRX(UC, BS, BC, DOCONS, DOOUT, DOSTORE, DOPREF)                   \
    do {                                                                    \
        float4 n0, n1;                                                      \
        if (DOPREF) {                                                       \
            n0 = *(const float4*)rp;                                        \
            n1 = *(const float4*)(rp + IMG_W);                              \
            rp += 2 * IMG_W;                                                \
        }                                                                   \
        int4 A0, B0, C0, A1, B1, C1;                                        \
        if (DOCONS) {                                                       \
            const int* rb0 = rowbuf[2 * (BC)];                              \
            const int* rb1 = rowbuf[2 * (BC) + 1];                          \
            A0 = *(const int4*)(rb0 + c0);                                  \
            B0 = *(const int4*)(rb0 + c0 + 4);                              \
            C0 = *(const int4*)(rb0 + c0 + 8);                              \
            A1 = *(const int4*)(rb1 + c0);                                  \
            B1 = *(const int4*)(rb1 + c0 + 4);                              \
            C1 = *(const int4*)(rb1 + c0 + 8);                              \
        }                                                                   \
        if (DOSTORE) {                                                      \
            int a0 = fsig_q(cur0.x), a1 = fsig_q(cur0.y);                   \
            int a2 = fsig_q(cur0.z), a3 = fsig_q(cur0.w);                   \
            int b0 = fsig_q(cur1.x), b1 = fsig_q(cur1.y);                   \
            int b2 = fsig_q(cur1.z), b3 = fsig_q(cur1.w);                   \
            *(int4*)(rowbuf[2 * (BS)] + 4 + c0) = make_int4(a0, a1, a2, a3);\
            *(int4*)(rowbuf[2 * (BS) + 1] + 4 + c0) = make_int4(b0, b1, b2, b3); \
        }                                                                   \
        __syncthreads();                                                    \
        if (DOCONS) {                                                       \
            CONS_ROW((UC),     A0, B0, C0, DOOUT, accv, acc_e, acc_l);      \
            CONS_ROW((UC) + 1, A1, B1, C1, DOOUT, accv, acc_e, acc_l);      \
        }                                                                   \
        if (DOPREF) { cur0 = n0; cur1 = n1; }                               \
    } while (0)

        // k=0: store rows 0,1; prefetch 2,3; no consume
        PAIRX(0, 0, 0, false, false, true, true);
        // k=1..4: consume rows 0..7 (outputs at 6,7)
        PAIRX(0, 1, 0, true, false, true, true);
        PAIRX(2, 0, 1, true, false, true, true);
        PAIRX(4, 1, 0, true, false, true, true);
        PAIRX(6, 0, 1, true, true,  true, true);
        // k=5..32: consume rows 8..63, all outputs
        for (int ii = 0; ii < 7; ++ii) {
            PAIRX(0, 1, 0, true, true, true, true);
            PAIRX(2, 0, 1, true, true, true, true);
            PAIRX(4, 1, 0, true, true, true, true);
            PAIRX(6, 0, 1, true, true, true, true);
        }
        // k=33: consume 64,65; store 66,67; prefetch 68,69
        PAIRX(0, 1, 0, true, true, true, true);
        // k=34: consume 66,67; store 68,69; no prefetch
        PAIRX(2, 0, 1, true, true, true, false);
        // k=35: drain — consume 68,69 only
        PAIRX(4, 1, 0, true, true, false, false);
#undef PAIRX

        // per-pixel weight = cnt/49 = (7*cw)/49 ; descale d_i by SV
        float acc_v_tot = 0.f;
        #pragma unroll
        for (int j = 0; j < 4; ++j)
            acc_v_tot = fmaf(accv[j], cwf[j], acc_v_tot);
        float acc_e_tot = fmaf(0.5f, acc_l, acc_e);
        acc = AALPHA * acc_e_tot * SE
            + ((1.0f - AALPHA) / 49.0f) * 7.0f * acc_v_tot * (SV * SV);
    } else {
        // ================= guarded path (blocks 0 and 15), per-row =========
        float acc_e = 0.f, acc_l = 0.f, acc_v = 0.f;

        float4 cur = make_float4(0.f, 0.f, 0.f, 0.f);
        {
            int gy = y0 - 3;
            if ((unsigned)gy < IMG_H)
                cur = *(const float4*)(base + (size_t)gy * IMG_W + c0);
        }
        for (int ii = 0; ii < 72; ii += 8) {
            #pragma unroll
            for (int u = 0; u < 8; ++u) {
                const int i  = ii + u;
                const int gy = y0 - 3 + i;
                const bool valid = ((unsigned)gy < IMG_H) && (i < 70);

                float4 nxt = make_float4(0.f, 0.f, 0.f, 0.f);
                {
                    int gyn = gy + 1;
                    if ((unsigned)gyn < IMG_H && (i + 1) < 70)
                        nxt = *(const float4*)(base + (size_t)gyn * IMG_W + c0);
                }
                int m0 = valid ? fsig_q(cur.x) : 0;
                int m1 = valid ? fsig_q(cur.y) : 0;
                int m2 = valid ? fsig_q(cur.z) : 0;
                int m3 = valid ? fsig_q(cur.w) : 0;
                int* rb = rowbuf[u & 1];
                *(int4*)(rb + 4 + c0) = make_int4(m0, m1, m2, m3);
                __syncthreads();

                const int4 A = *(const int4*)(rb + c0);
                const int4 C = *(const int4*)(rb + c0 + 8);

                int h0 = ((A.y + A.z) + (A.w + m0)) + ((m1 + m2) + m3);
                int h1 = h0 + C.x - A.y;
                int h2 = h1 + C.y - A.z;
                int h3 = h2 + C.z - A.w;

                vs[0] += h0 - hr[(u + 1) & 7][0];
                vs[1] += h1 - hr[(u + 1) & 7][1];
                vs[2] += h2 - hr[(u + 1) & 7][2];
                vs[3] += h3 - hr[(u + 1) & 7][3];
                hr[u][0] = h0; hr[u][1] = h1; hr[u][2] = h2; hr[u][3] = h3;

                if (i >= 6 && i < 70) {
                    const int yo = gy - 3;
                    const float chf = (float)(min(yo, 3) + min(IMG_H - 1 - yo, 3) + 1);
                    const int T = u & 3, M = (u + 1) & 3, Bo = (u + 2) & 3;
                    float rowv = 0.f;
                    int lrow = 0;
                    #pragma unroll
                    for (int j = 0; j < 4; ++j) {
                        int gxi = rti[T][j] + 2 * rti[M][j] + rti[Bo][j];
                        int gyi = rsi[T][j] - rsi[Bo][j];
                        int lpi = (rci[T][j] + rci[Bo][j]) + rsi[M][j] - 6 * rci[M][j];
                        float gxf = __int2float_rn(gxi);
                        float gyf = __int2float_rn(gyi);
                        acc_e += fsqrt_fast(fmaf(gxf, gxf, gyf * gyf));
                        lrow += abs(lpi);
                        int di = 49 * rci[M][j] - vs[j];
                        float df = __int2float_rn(di);
                        rowv = fmaf(df * cwf[j], df, rowv);
                    }
                    acc_l += __int2float_rn(lrow);
                    acc_v += chf * rowv;
                }

                const int W = u & 3;
                rsi[W][0] = 2 * m0 + (A.w + m1); rti[W][0] = A.w - m1; rci[W][0] = m0;
                rsi[W][1] = 2 * m1 + (m0 + m2);  rti[W][1] = m0 - m2;  rci[W][1] = m1;
                rsi[W][2] = 2 * m2 + (m1 + m3);  rti[W][2] = m1 - m3;  rci[W][2] = m2;
                rsi[W][3] = 2 * m3 + (m2 + C.x); rti[W][3] = m2 - C.x; rci[W][3] = m3;

                cur = nxt;
            }
        }
        float acc_e_tot = fmaf(0.5f, acc_l, acc_e);
        acc = AALPHA * acc_e_tot * SE
            + ((1.0f - AALPHA) / 49.0f) * acc_v * (SV * SV);
    }
#undef CONS_ROW

    // block reduction -> per-block partial
    #pragma unroll
    for (int off = 16; off; off >>= 1)
        acc += __shfl_down_sync(0xffffffffu, acc, off);
    if ((t & 31) == 0) red[t >> 5] = acc;
    __syncthreads();
    if (t < 8) {
        float v = red[t];
        #pragma unroll
        for (int off = 4; off; off >>= 1)
            v += __shfl_down_sync(0xffu, v, off);
        if (t == 0) g_part[img * BPI + blockIdx.x] = v;
    }
}

// ---------------------------------------------------------------------------
// reduce partials; weights[b,s] = 0.5*(score/(sum+1e-6) + softmax(lw)[s])
// ---------------------------------------------------------------------------
__global__ void weights_kernel(const float* __restrict__ lw) {
    __shared__ float ss[NIMG];
    __shared__ float soft[3];
    int tid = threadIdx.x;
    if (tid < NIMG) {
        float s = 0.f;
        #pragma unroll
        for (int k = 0; k < BPI; ++k) s += g_part[tid * BPI + k];
        ss[tid] = s;
    }
    if (tid == 0) {
        float a = lw[0], b = lw[1], c = lw[2];
        float m = fmaxf(a, fmaxf(b, c));
        float e0 = expf(a - m), e1 = expf(b - m), e2 = expf(c - m);
        float inv = 1.0f / (e0 + e1 + e2);
        soft[0] = e0 * inv; soft[1] = e1 * inv; soft[2] = e2 * inv;
    }
    __syncthreads();
    if (tid < NIMG) {
        int b = tid / 3;
        int s = tid - b * 3;
        float denom = ss[b * 3] + ss[b * 3 + 1] + ss[b * 3 + 2] + 1e-6f;
        g_weights[tid] = (ss[tid] / denom + soft[s]) * 0.5f;
    }
}

// ---------------------------------------------------------------------------
// fused[b,p] = sum_s logits[b,s,p] * w[b,s]   (float4 vectorized)
// ---------------------------------------------------------------------------
__global__ __launch_bounds__(256) void fuse_kernel(const float* __restrict__ logits,
                                                   float* __restrict__ out) {
    const int N = IMG_H * IMG_W;
    int b = blockIdx.y;
    int i = blockIdx.x * blockDim.x + threadIdx.x;   // over N/4
    float w0 = g_weights[b * 3 + 0];
    float w1 = g_weights[b * 3 + 1];
    float w2 = g_weights[b * 3 + 2];
    const float4* p0 = (const float4*)(logits + (size_t)(b * 3 + 0) * N);
    const float4* p1 = (const float4*)(logits + (size_t)(b * 3 + 1) * N);
    const float4* p2 = (const float4*)(logits + (size_t)(b * 3 + 2) * N);
    float4 a = p0[i], bb = p1[i], cc = p2[i];
    float4 o;
    o.x = a.x * w0 + bb.x * w1 + cc.x * w2;
    o.y = a.y * w0 + bb.y * w1 + cc.y * w2;
    o.z = a.z * w0 + bb.z * w1 + cc.z * w2;
    o.w = a.w * w0 + bb.w * w1 + cc.w * w2;
    ((float4*)out)[(size_t)b * (N / 4) + i] = o;
}

extern "C" void kernel_launch(void* const* d_in, const int* in_sizes, int n_in,
                              void* d_out, int out_size) {
    const float* logits = (const float*)d_in[0];   // (16,3,1024,1024) fp32
    const float* lw     = (const float*)d_in[1];   // (3,) fp32
    float* out          = (float*)d_out;           // (16,1024,1024) fp32

    score_kernel<<<dim3(BPI, NIMG), 256>>>(logits);
    weights_kernel<<<1, 64>>>(lw);
    fuse_kernel<<<dim3((IMG_H * IMG_W / 4) / 256, 16), 256>>>(logits, out);
}

// round 14
// speedup vs baseline: 1.0613x; 1.0337x over previous
#include <cuda_runtime.h>

#define AALPHA 0.42f
#define IMG_H 1024
#define IMG_W 1024
#define NIMG 48     // 16 batches * 3 masks
#define RPB 64      // output rows per block
#define BPI 16      // blocks per image (IMG_H / RPB)

#define QS 1048576.0f            // 2^20 quantization scale
#define SE (1.0f / 1048576.0f)   // descale
#define SV (1.0f / (49.0f * 1048576.0f))  // guarded-path d descale

__device__ float g_part[NIMG * BPI];
__device__ float g_weights[NIMG];

// quantized sigmoid: round(sigmoid(x) * 2^20)
__device__ __forceinline__ int fsig_q(float x) {
    float t;
    asm("tanh.approx.f32 %0, %1;" : "=f"(t) : "f"(0.5f * x));
    return __float2int_rn(fmaf(0.5f * QS, t, 0.5f * QS));
}
__device__ __forceinline__ float fsqrt_fast(float x) {
    float r; asm("sqrt.approx.f32 %0, %1;" : "=f"(r) : "f"(x)); return r;
}

// ---------------------------------------------------------------------------
// score = ALPHA * sum(edge) + (1-ALPHA)/49 * sum( cnt(p) * (m_p - mean_p)^2 )
// HYBRID: window sums (h-chain, vertical slide) in exact int32 (IADD3, alu
// pipe); conv ring + output math in float (fma pipe) from I2F'd row values.
// Balances fma ~116 / alu ~55 cyc per warp-row (vs 152/20 all-float and
// 44/176 all-int). R13 pair-pipelined structure + fixed halo init.
// ---------------------------------------------------------------------------
__global__ __launch_bounds__(256, 2) void score_kernel(const float* __restrict__ logits) {
    __shared__ int rowbuf[4][1032];   // quantized m, cols -4..1027, data at +4
    __shared__ float red[8];

    const int img = blockIdx.y;
    const int y0  = blockIdx.x * RPB;
    const int t   = threadIdx.x;
    const int c0  = t * 4;
    const float* base = logits + (size_t)img * (IMG_H * IMG_W);

    // zero halo columns of all four buffers: idx {0..3, 1028..1031}
    if (t < 32) {
        int b = t >> 3, j = t & 7;
        rowbuf[b][(j < 4) ? j : (1024 + j)] = 0;
    }

    int hr[8][4];        // horizontal-7-sum ring (int, exact)
    int vs[4] = {0, 0, 0, 0};
    #pragma unroll
    for (int k = 0; k < 8; ++k) { hr[k][0]=hr[k][1]=hr[k][2]=hr[k][3]=0; }

    float cwf[4];
    #pragma unroll
    for (int j = 0; j < 4; ++j) {
        int col = c0 + j;
        cwf[j] = (float)(min(col, 3) + min(IMG_W - 1 - col, 3) + 1);
    }

    float acc;

    if (blockIdx.x >= 1 && blockIdx.x <= 14) {
        // ================= clean path: all rows in-bounds, ch = 7 ==========
        float rsf[4][4], rtf[4][4], rcf[4][4];   // conv combo ring (float)
        #pragma unroll
        for (int k = 0; k < 4; ++k) {
            #pragma unroll
            for (int j = 0; j < 4; ++j) { rsf[k][j]=0.f; rtf[k][j]=0.f; rcf[k][j]=0.f; }
        }
        float accv[4] = {0.f, 0.f, 0.f, 0.f};
        float acc_e = 0.f, acc_l = 0.f;

// consume one row from int registers A,B,C. int h/vs; float conv/output.
#define CONS_ROW(U, A, B, C, DOOUT)                                         \
    do {                                                                    \
        int h0 = ((A.y + A.z) + (A.w + B.x)) + ((B.y + B.z) + B.w);         \
        int h1 = h0 + C.x - A.y;                                            \
        int h2 = h1 + C.y - A.z;                                            \
        int h3 = h2 + C.z - A.w;                                            \
        vs[0] += h0 - hr[((U) + 1) & 7][0];                                 \
        vs[1] += h1 - hr[((U) + 1) & 7][1];                                 \
        vs[2] += h2 - hr[((U) + 1) & 7][2];                                 \
        vs[3] += h3 - hr[((U) + 1) & 7][3];                                 \
        hr[(U) & 7][0] = h0; hr[(U) & 7][1] = h1;                           \
        hr[(U) & 7][2] = h2; hr[(U) & 7][3] = h3;                           \
        float awf = __int2float_rn(A.w);                                    \
        float b0f = __int2float_rn(B.x);                                    \
        float b1f = __int2float_rn(B.y);                                    \
        float b2f = __int2float_rn(B.z);                                    \
        float b3f = __int2float_rn(B.w);                                    \
        float cxf = __int2float_rn(C.x);                                    \
        if (DOOUT) {                                                        \
            const int T = (U) & 3, M = ((U) + 1) & 3, Bo = ((U) + 2) & 3;   \
            _Pragma("unroll")                                               \
            for (int j = 0; j < 4; ++j) {                                   \
                float gxv = fmaf(2.f, rtf[M][j], rtf[T][j] + rtf[Bo][j]);   \
                float gyv = rsf[T][j] - rsf[Bo][j];                         \
                float lap = fmaf(-6.f, rcf[M][j],                           \
                                 (rcf[T][j] + rcf[Bo][j]) + rsf[M][j]);     \
                acc_e += fsqrt_fast(fmaf(gxv, gxv, gyv * gyv));             \
                acc_l += fabsf(lap);                                        \
                float vsf = __int2float_rn(vs[j]);                          \
                float d = fmaf(-(1.f / 49.f), vsf, rcf[M][j]);              \
                accv[j] = fmaf(d, d, accv[j]);                              \
            }                                                               \
        }                                                                   \
        const int W = (U) & 3;                                              \
        rsf[W][0] = fmaf(2.f, b0f, awf + b1f); rtf[W][0] = awf - b1f; rcf[W][0] = b0f; \
        rsf[W][1] = fmaf(2.f, b1f, b0f + b2f); rtf[W][1] = b0f - b2f; rcf[W][1] = b1f; \
        rsf[W][2] = fmaf(2.f, b2f, b1f + b3f); rtf[W][2] = b1f - b3f; rcf[W][2] = b2f; \
        rsf[W][3] = fmaf(2.f, b3f, b2f + cxf); rtf[W][3] = b2f - cxf; rcf[W][3] = b3f; \
    } while (0)

        const float* rp = base + (size_t)(y0 - 3) * IMG_W + c0;
        float4 cur0 = *(const float4*)rp;
        float4 cur1 = *(const float4*)(rp + IMG_W);
        rp += 2 * IMG_W;

// pair-iteration: consume rows UC,UC+1 from buf-pair BC (LDS pre-BAR),
// store current pair into buf-pair BS, prefetch next pair. Flags static.
#define PAIRX(UC, BS, BC, DOCONS, DOOUT, DOSTORE, DOPREF)                   \
    do {                                                                    \
        float4 n0, n1;                                                      \
        if (DOPREF) {                                                       \
            n0 = *(const float4*)rp;                                        \
            n1 = *(const float4*)(rp + IMG_W);                              \
            rp += 2 * IMG_W;                                                \
        }                                                                   \
        int4 A0, B0, C0, A1, B1, C1;                                        \
        if (DOCONS) {                                                       \
            const int* rb0 = rowbuf[2 * (BC)];                              \
            const int* rb1 = rowbuf[2 * (BC) + 1];                          \
            A0 = *(const int4*)(rb0 + c0);                                  \
            B0 = *(const int4*)(rb0 + c0 + 4);                              \
            C0 = *(const int4*)(rb0 + c0 + 8);                              \
            A1 = *(const int4*)(rb1 + c0);                                  \
            B1 = *(const int4*)(rb1 + c0 + 4);                              \
            C1 = *(const int4*)(rb1 + c0 + 8);                              \
        }                                                                   \
        if (DOSTORE) {                                                      \
            int a0 = fsig_q(cur0.x), a1 = fsig_q(cur0.y);                   \
            int a2 = fsig_q(cur0.z), a3 = fsig_q(cur0.w);                   \
            int b0 = fsig_q(cur1.x), b1 = fsig_q(cur1.y);                   \
            int b2 = fsig_q(cur1.z), b3 = fsig_q(cur1.w);                   \
            *(int4*)(rowbuf[2 * (BS)] + 4 + c0) = make_int4(a0, a1, a2, a3);\
            *(int4*)(rowbuf[2 * (BS) + 1] + 4 + c0) = make_int4(b0, b1, b2, b3); \
        }                                                                   \
        __syncthreads();                                                    \
        if (DOCONS) {                                                       \
            CONS_ROW((UC),     A0, B0, C0, DOOUT);                          \
            CONS_ROW((UC) + 1, A1, B1, C1, DOOUT);                          \
        }                                                                   \
        if (DOPREF) { cur0 = n0; cur1 = n1; }                               \
    } while (0)

        // k=0: store rows 0,1; prefetch 2,3; no consume
        PAIRX(0, 0, 0, false, false, true, true);
        // rows 0..7 (outputs at 6,7)
        PAIRX(0, 1, 0, true, false, true, true);
        PAIRX(2, 0, 1, true, false, true, true);
        PAIRX(4, 1, 0, true, false, true, true);
        PAIRX(6, 0, 1, true, true,  true, true);
        // rows 8..63
        for (int ii = 0; ii < 7; ++ii) {
            PAIRX(0, 1, 0, true, true, true, true);
            PAIRX(2, 0, 1, true, true, true, true);
            PAIRX(4, 1, 0, true, true, true, true);
            PAIRX(6, 0, 1, true, true, true, true);
        }
        // tail: consume 64..69
        PAIRX(0, 1, 0, true, true, true, true);
        PAIRX(2, 0, 1, true, true, true, false);
        PAIRX(4, 1, 0, true, true, false, false);
#undef PAIRX
#undef CONS_ROW

        // cnt = 7*cw ; all scaled quantities carry 2^20
        float acc_v_tot = 0.f;
        #pragma unroll
        for (int j = 0; j < 4; ++j)
            acc_v_tot = fmaf(accv[j], cwf[j], acc_v_tot);
        float acc_e_tot = fmaf(0.5f, acc_l, acc_e);
        acc = AALPHA * acc_e_tot * SE
            + ((1.0f - AALPHA) / 49.0f) * 7.0f * acc_v_tot * (SE * SE);
    } else {
        // ================= guarded path (blocks 0 and 15): R13 int =========
        int rsi[4][4], rti[4][4], rci[4][4];
        #pragma unroll
        for (int k = 0; k < 4; ++k) {
            #pragma unroll
            for (int j = 0; j < 4; ++j) { rsi[k][j]=0; rti[k][j]=0; rci[k][j]=0; }
        }
        float acc_e = 0.f, acc_l = 0.f, acc_v = 0.f;

        float4 cur = make_float4(0.f, 0.f, 0.f, 0.f);
        {
            int gy = y0 - 3;
            if ((unsigned)gy < IMG_H)
                cur = *(const float4*)(base + (size_t)gy * IMG_W + c0);
        }
        for (int ii = 0; ii < 72; ii += 8) {
            #pragma unroll
            for (int u = 0; u < 8; ++u) {
                const int i  = ii + u;
                const int gy = y0 - 3 + i;
                const bool valid = ((unsigned)gy < IMG_H) && (i < 70);

                float4 nxt = make_float4(0.f, 0.f, 0.f, 0.f);
                {
                    int gyn = gy + 1;
                    if ((unsigned)gyn < IMG_H && (i + 1) < 70)
                        nxt = *(const float4*)(base + (size_t)gyn * IMG_W + c0);
                }
                int m0 = valid ? fsig_q(cur.x) : 0;
                int m1 = valid ? fsig_q(cur.y) : 0;
                int m2 = valid ? fsig_q(cur.z) : 0;
                int m3 = valid ? fsig_q(cur.w) : 0;
                int* rb = rowbuf[u & 1];
                *(int4*)(rb + 4 + c0) = make_int4(m0, m1, m2, m3);
                __syncthreads();

                const int4 A = *(const int4*)(rb + c0);
                const int4 C = *(const int4*)(rb + c0 + 8);

                int h0 = ((A.y + A.z) + (A.w + m0)) + ((m1 + m2) + m3);
                int h1 = h0 + C.x - A.y;
                int h2 = h1 + C.y - A.z;
                int h3 = h2 + C.z - A.w;

                vs[0] += h0 - hr[(u + 1) & 7][0];
                vs[1] += h1 - hr[(u + 1) & 7][1];
                vs[2] += h2 - hr[(u + 1) & 7][2];
                vs[3] += h3 - hr[(u + 1) & 7][3];
                hr[u][0] = h0; hr[u][1] = h1; hr[u][2] = h2; hr[u][3] = h3;

                if (i >= 6 && i < 70) {
                    const int yo = gy - 3;
                    const float chf = (float)(min(yo, 3) + min(IMG_H - 1 - yo, 3) + 1);
                    const int T = u & 3, M = (u + 1) & 3, Bo = (u + 2) & 3;
                    float rowv = 0.f;
                    int lrow = 0;
                    #pragma unroll
                    for (int j = 0; j < 4; ++j) {
                        int gxi = rti[T][j] + 2 * rti[M][j] + rti[Bo][j];
                        int gyi = rsi[T][j] - rsi[Bo][j];
                        int lpi = (rci[T][j] + rci[Bo][j]) + rsi[M][j] - 6 * rci[M][j];
                        float gxf = __int2float_rn(gxi);
                        float gyf = __int2float_rn(gyi);
                        acc_e += fsqrt_fast(fmaf(gxf, gxf, gyf * gyf));
                        lrow += abs(lpi);
                        int di = 49 * rci[M][j] - vs[j];
                        float df = __int2float_rn(di);
                        rowv = fmaf(df * cwf[j], df, rowv);
                    }
                    acc_l += __int2float_rn(lrow);
                    acc_v += chf * rowv;
                }

                const int W = u & 3;
                rsi[W][0] = 2 * m0 + (A.w + m1); rti[W][0] = A.w - m1; rci[W][0] = m0;
                rsi[W][1] = 2 * m1 + (m0 + m2);  rti[W][1] = m0 - m2;  rci[W][1] = m1;
                rsi[W][2] = 2 * m2 + (m1 + m3);  rti[W][2] = m1 - m3;  rci[W][2] = m2;
                rsi[W][3] = 2 * m3 + (m2 + C.x); rti[W][3] = m2 - C.x; rci[W][3] = m3;

                cur = nxt;
            }
        }
        float acc_e_tot = fmaf(0.5f, acc_l, acc_e);
        acc = AALPHA * acc_e_tot * SE
            + ((1.0f - AALPHA) / 49.0f) * acc_v * (SV * SV);
    }

    // block reduction -> per-block partial
    #pragma unroll
    for (int off = 16; off; off >>= 1)
        acc += __shfl_down_sync(0xffffffffu, acc, off);
    if ((t & 31) == 0) red[t >> 5] = acc;
    __syncthreads();
    if (t < 8) {
        float v = red[t];
        #pragma unroll
        for (int off = 4; off; off >>= 1)
            v += __shfl_down_sync(0xffu, v, off);
        if (t == 0) g_part[img * BPI + blockIdx.x] = v;
    }
}

// ---------------------------------------------------------------------------
// reduce partials; weights[b,s] = 0.5*(score/(sum+1e-6) + softmax(lw)[s])
// ---------------------------------------------------------------------------
__global__ void weights_kernel(const float* __restrict__ lw) {
    __shared__ float ss[NIMG];
    __shared__ float soft[3];
    int tid = threadIdx.x;
    if (tid < NIMG) {
        float s = 0.f;
        #pragma unroll
        for (int k = 0; k < BPI; ++k) s += g_part[tid * BPI + k];
        ss[tid] = s;
    }
    if (tid == 0) {
        float a = lw[0], b = lw[1], c = lw[2];
        float m = fmaxf(a, fmaxf(b, c));
        float e0 = expf(a - m), e1 = expf(b - m), e2 = expf(c - m);
        float inv = 1.0f / (e0 + e1 + e2);
        soft[0] = e0 * inv; soft[1] = e1 * inv; soft[2] = e2 * inv;
    }
    __syncthreads();
    if (tid < NIMG) {
        int b = tid / 3;
        int s = tid - b * 3;
        float denom = ss[b * 3] + ss[b * 3 + 1] + ss[b * 3 + 2] + 1e-6f;
        g_weights[tid] = (ss[tid] / denom + soft[s]) * 0.5f;
    }
}

// ---------------------------------------------------------------------------
// fused[b,p] = sum_s logits[b,s,p] * w[b,s]   (float4 vectorized)
// ---------------------------------------------------------------------------
__global__ __launch_bounds__(256) void fuse_kernel(const float* __restrict__ logits,
                                                   float* __restrict__ out) {
    const int N = IMG_H * IMG_W;
    int b = blockIdx.y;
    int i = blockIdx.x * blockDim.x + threadIdx.x;   // over N/4
    float w0 = g_weights[b * 3 + 0];
    float w1 = g_weights[b * 3 + 1];
    float w2 = g_weights[b * 3 + 2];
    const float4* p0 = (const float4*)(logits + (size_t)(b * 3 + 0) * N);
    const float4* p1 = (const float4*)(logits + (size_t)(b * 3 + 1) * N);
    const float4* p2 = (const float4*)(logits + (size_t)(b * 3 + 2) * N);
    float4 a = p0[i], bb = p1[i], cc = p2[i];
    float4 o;
    o.x = a.x * w0 + bb.x * w1 + cc.x * w2;
    o.y = a.y * w0 + bb.y * w1 + cc.y * w2;
    o.z = a.z * w0 + bb.z * w1 + cc.z * w2;
    o.w = a.w * w0 + bb.w * w1 + cc.w * w2;
    ((float4*)out)[(size_t)b * (N / 4) + i] = o;
}

extern "C" void kernel_launch(void* const* d_in, const int* in_sizes, int n_in,
                              void* d_out, int out_size) {
    const float* logits = (const float*)d_in[0];   // (16,3,1024,1024) fp32
    const float* lw     = (const float*)d_in[1];   // (3,) fp32
    float* out          = (float*)d_out;           // (16,1024,1024) fp32

    score_kernel<<<dim3(BPI, NIMG), 256>>>(logits);
    weights_kernel<<<1, 64>>>(lw);
    fuse_kernel<<<dim3((IMG_H * IMG_W / 4) / 256, 16), 256>>>(logits, out);
}